// round 10
// baseline (speedup 1.0000x reference)
#include <cuda_runtime.h>
#include <cstdint>

// SplitMLP, tf32 mma.sync + persistent CTAs + double-buffered cp.async pipeline.
// R8: 256 threads/CTA (8 warps, 16 rows each) to fix latency-hiding deficit.
// Per group g: h = relu(A @ Wcat^T + b1); y = h @ W2^T + b2
//   A    = [day | items[:,g,:]] : 128 x 48 K-major  (day staged once, static)
//   Wcat = [W1_day | W1_var][g]: 64 x 48  K-major

#define B_ 128
#define C_ 16
#define V_ 32
#define H_ 64
#define O_ 4
#define G_ 10000

#define THREADS 256
#define GRID 296            // 2 CTAs/SM x 148 SMs, persistent

// smem row strides (floats) — ldmatrix-phase conflict-free
#define KS_D 20             // day   tile: 128 x 16  (80B rows)
#define KS_I 36             // items tile: 128 x 32  (144B rows)
#define KS_B 52             // Wcat  tile:  64 x 48  (208B rows)

#define SZ_DAY (B_ * KS_D * 4)              // 10240
#define SZ_AI  (B_ * KS_I * 4)              // 18432
#define SZ_B   (H_ * KS_B * 4)              // 13312
#define SZ_W2  (O_ * H_ * 4)                // 1024
#define SZ_B1  (H_ * 4)                     // 256
#define SZ_B2  16
#define BUF_SZ (SZ_AI + SZ_B + SZ_W2 + SZ_B1 + SZ_B2)   // 33040
#define SMEM_TOTAL (SZ_DAY + 2 * BUF_SZ)                 // 76320

__device__ __forceinline__ uint32_t s2u(const void* p) {
    uint32_t a;
    asm("{ .reg .u64 t; cvta.to.shared.u64 t, %1; cvt.u32.u64 %0, t; }"
        : "=r"(a) : "l"(p));
    return a;
}

__device__ __forceinline__ void cpa16(uint32_t dst, const void* src) {
    asm volatile("cp.async.cg.shared.global [%0], [%1], 16;"
                 :: "r"(dst), "l"(src) : "memory");
}

__device__ __forceinline__ void ldsm4(uint32_t& r0, uint32_t& r1,
                                      uint32_t& r2, uint32_t& r3, uint32_t addr) {
    asm volatile("ldmatrix.sync.aligned.m8n8.x4.shared.b16 {%0,%1,%2,%3}, [%4];"
                 : "=r"(r0), "=r"(r1), "=r"(r2), "=r"(r3) : "r"(addr));
}

__device__ __forceinline__ void mma_tf32(float* d, const uint32_t* a, const uint32_t* b) {
    asm volatile(
        "mma.sync.aligned.m16n8k8.row.col.f32.tf32.tf32.f32 "
        "{%0,%1,%2,%3}, {%4,%5,%6,%7}, {%8,%9}, {%0,%1,%2,%3};"
        : "+f"(d[0]), "+f"(d[1]), "+f"(d[2]), "+f"(d[3])
        : "r"(a[0]), "r"(a[1]), "r"(a[2]), "r"(a[3]), "r"(b[0]), "r"(b[1]));
}

// stage one group's per-group data (items, W1_day, W1_var, W2, b1, b2) async
__device__ __forceinline__ void stage_group(
    uint32_t bufU, int g, int tid,
    const float* __restrict__ items, const float* __restrict__ W1_day,
    const float* __restrict__ W1_var, const float* __restrict__ W2,
    const float* __restrict__ b1, const float* __restrict__ b2)
{
    // items: 128 rows x 8 granules (k local 0..31)
    #pragma unroll
    for (int i = tid; i < 1024; i += THREADS) {
        int b = i >> 3, v4 = i & 7;
        cpa16(bufU + b * (KS_I * 4) + v4 * 16,
              items + ((size_t)b * G_ + g) * V_ + v4 * 4);
    }
    const uint32_t bB = bufU + SZ_AI;
    // W1_day -> Wcat cols 0..15 (256 granules, one per thread)
    if (tid < 256) {
        int h = tid >> 2, c4 = tid & 3;
        cpa16(bB + h * (KS_B * 4) + c4 * 16,
              W1_day + (size_t)g * H_ * C_ + h * C_ + c4 * 4);
    }
    // W1_var -> Wcat cols 16..47 (512 granules)
    #pragma unroll
    for (int i = tid; i < 512; i += THREADS) {
        int h = i >> 3, v4 = i & 7;
        cpa16(bB + h * (KS_B * 4) + 64 + v4 * 16,
              W1_var + (size_t)g * H_ * V_ + h * V_ + v4 * 4);
    }
    const uint32_t bW2 = bufU + SZ_AI + SZ_B;
    if (tid >= 128) {
        int t = tid - 128;
        if (t < 64) {
            cpa16(bW2 + t * 16, W2 + (size_t)g * O_ * H_ + t * 4);
        } else if (t < 80) {
            cpa16(bW2 + SZ_W2 + (t - 64) * 16, b1 + (size_t)g * H_ + (t - 64) * 4);
        } else if (t == 80) {
            cpa16(bW2 + SZ_W2 + SZ_B1, b2 + (size_t)g * O_);
        }
    }
}

__global__ void __launch_bounds__(THREADS)
splitmlp_pipe_kernel(const float* __restrict__ day,
                     const float* __restrict__ items,
                     const float* __restrict__ W1_day,
                     const float* __restrict__ W1_var,
                     const float* __restrict__ b1,
                     const float* __restrict__ W2,
                     const float* __restrict__ b2,
                     float* __restrict__ out)
{
    extern __shared__ __align__(128) char sm[];
    const uint32_t sbase = s2u(sm);
    const uint32_t dayU  = sbase;
    const int tid  = threadIdx.x;
    const int lane = tid & 31;
    const int wid  = tid >> 5;          // 0..7, warp owns rows 16*wid..16*wid+15

    // ---- stage day once (joins the first async group) ----
    #pragma unroll
    for (int i = tid; i < 512; i += THREADS) {
        int b = i >> 2, c4 = i & 3;
        cpa16(dayU + b * (KS_D * 4) + c4 * 16, day + b * C_ + c4 * 4);
    }

    const int g0 = blockIdx.x;
    if (g0 >= G_) return;

    // ---- prologue: stage first group into buffer 0 ----
    stage_group(sbase + SZ_DAY, g0, tid, items, W1_day, W1_var, W2, b1, b2);
    asm volatile("cp.async.commit_group;" ::: "memory");

    // ldmatrix base addresses (b16 view of tf32 tiles)
    const int rsel = lane & 15, hsel = (lane >> 4) * 16;
    const uint32_t dayAddr = dayU + (16 * wid + rsel) * (KS_D * 4) + hsel;

    int it = 0;
    for (int g = g0; g < G_; g += GRID, it++) {
        const uint32_t curU = sbase + SZ_DAY + (uint32_t)(it & 1) * BUF_SZ;
        const char*    curP = sm + SZ_DAY + (size_t)(it & 1) * BUF_SZ;

        const int gn = g + GRID;
        if (gn < G_) {
            stage_group(sbase + SZ_DAY + (uint32_t)((it + 1) & 1) * BUF_SZ,
                        gn, tid, items, W1_day, W1_var, W2, b1, b2);
            asm volatile("cp.async.commit_group;" ::: "memory");
            asm volatile("cp.async.wait_group 1;" ::: "memory");
        } else {
            asm volatile("cp.async.wait_group 0;" ::: "memory");
        }
        __syncthreads();

        // ---- fc1 mainloop: warp owns 16 rows, all 64 cols ----
        const uint32_t aiAddr = curU + (16 * wid + rsel) * (KS_I * 4) + hsel;
        const uint32_t bAddr  = curU + SZ_AI + rsel * (KS_B * 4) + hsel;

        float acc[8][4];
        #pragma unroll
        for (int nt = 0; nt < 8; nt++)
            #pragma unroll
            for (int c = 0; c < 4; c++)
                acc[nt][c] = 0.0f;

        #pragma unroll
        for (int ks = 0; ks < 6; ks++) {               // K = 48 = 6 x 8
            uint32_t a[4];
            if (ks < 2)                                // day part (k 0..15)
                ldsm4(a[0], a[1], a[2], a[3], dayAddr + ks * 32);
            else                                       // items part (k 16..47)
                ldsm4(a[0], a[1], a[2], a[3], aiAddr + (ks - 2) * 32);

            uint32_t bf[8][2];
            #pragma unroll
            for (int np = 0; np < 4; np++) {
                uint32_t r0, r1, r2, r3;
                ldsm4(r0, r1, r2, r3, bAddr + np * 16 * (KS_B * 4) + ks * 32);
                bf[2 * np + 0][0] = r0; bf[2 * np + 0][1] = r2;
                bf[2 * np + 1][0] = r1; bf[2 * np + 1][1] = r3;
            }
            #pragma unroll
            for (int nt = 0; nt < 8; nt++)
                mma_tf32(acc[nt], a, bf[nt]);
        }

        // ---- epilogue: bias + ReLU + fc2 in registers ----
        const float* W2s = (const float*)(curP + SZ_AI + SZ_B);
        const float* b1s = (const float*)(curP + SZ_AI + SZ_B + SZ_W2);
        const float* b2s = (const float*)(curP + SZ_AI + SZ_B + SZ_W2 + SZ_B1);

        float y[2][4];
        #pragma unroll
        for (int j = 0; j < 2; j++)
            #pragma unroll
            for (int o = 0; o < O_; o++)
                y[j][o] = 0.0f;

        #pragma unroll
        for (int nt = 0; nt < 8; nt++) {
            const int h0 = nt * 8 + 2 * (lane & 3);
            float2 bb = *(const float2*)&b1s[h0];
            float2 w0 = *(const float2*)&W2s[0 * H_ + h0];
            float2 w1 = *(const float2*)&W2s[1 * H_ + h0];
            float2 w2 = *(const float2*)&W2s[2 * H_ + h0];
            float2 w3 = *(const float2*)&W2s[3 * H_ + h0];
            #pragma unroll
            for (int hh = 0; hh < 2; hh++) {
                float v0 = fmaxf(acc[nt][hh * 2 + 0] + bb.x, 0.0f);
                float v1 = fmaxf(acc[nt][hh * 2 + 1] + bb.y, 0.0f);
                y[hh][0] = fmaf(v0, w0.x, fmaf(v1, w0.y, y[hh][0]));
                y[hh][1] = fmaf(v0, w1.x, fmaf(v1, w1.y, y[hh][1]));
                y[hh][2] = fmaf(v0, w2.x, fmaf(v1, w2.y, y[hh][2]));
                y[hh][3] = fmaf(v0, w3.x, fmaf(v1, w3.y, y[hh][3]));
            }
        }

        #pragma unroll
        for (int m = 1; m < 4; m <<= 1)
            #pragma unroll
            for (int j = 0; j < 2; j++)
                #pragma unroll
                for (int o = 0; o < O_; o++)
                    y[j][o] += __shfl_xor_sync(0xffffffffu, y[j][o], m);

        if ((lane & 3) == 0) {
            const int r = lane >> 2;
            #pragma unroll
            for (int hh = 0; hh < 2; hh++) {
                const int b = 16 * wid + 8 * hh + r;
                float4 o4;
                o4.x = y[hh][0] + b2s[0];
                o4.y = y[hh][1] + b2s[1];
                o4.z = y[hh][2] + b2s[2];
                o4.w = y[hh][3] + b2s[3];
                *(float4*)(out + ((size_t)b * G_ + g) * O_) = o4;
            }
        }

        __syncthreads();   // buffer reuse: next-next stage writes over this one
    }
}

extern "C" void kernel_launch(void* const* d_in, const int* in_sizes, int n_in,
                              void* d_out, int out_size)
{
    const float* day    = (const float*)d_in[0];
    const float* items  = (const float*)d_in[1];
    const float* W1_day = (const float*)d_in[2];
    const float* W1_var = (const float*)d_in[3];
    const float* b1     = (const float*)d_in[4];
    const float* W2     = (const float*)d_in[5];
    const float* b2     = (const float*)d_in[6];
    float* out = (float*)d_out;

    static bool attr_done = false;
    if (!attr_done) {
        cudaFuncSetAttribute(splitmlp_pipe_kernel,
                             cudaFuncAttributeMaxDynamicSharedMemorySize, SMEM_TOTAL);
        attr_done = true;
    }
    splitmlp_pipe_kernel<<<GRID, THREADS, SMEM_TOTAL>>>(
        day, items, W1_day, W1_var, b1, W2, b2, out);
}

// round 11
// speedup vs baseline: 1.2296x; 1.2296x over previous
#include <cuda_runtime.h>
#include <cstdint>

// SplitMLP, tf32 mma.sync, persistent CTAs, double-buffered cp.async.
// R11: back to 128 thr / 4 warps (minimal LDSM duplication), day A-fragments
// hoisted to registers (group-invariant), smem 66.3KB -> 3 CTAs/SM.
//   A    = [day | items[:,g,:]] : 128 x 48 K-major
//   Wcat = [W1_day | W1_var][g]: 64 x 48  K-major

#define B_ 128
#define C_ 16
#define V_ 32
#define H_ 64
#define O_ 4
#define G_ 10000

#define THREADS 128
#define GRID 444            // 3 CTAs/SM x 148 SMs, persistent

// smem row strides (floats) — ldmatrix-phase conflict-free
#define KS_D 20             // day staging (transient, in buffer 1)
#define KS_I 36             // items tile: 128 x 32  (144B rows)
#define KS_B 52             // Wcat  tile:  64 x 48  (208B rows)

#define SZ_AI  (B_ * KS_I * 4)              // 18432
#define SZ_B   (H_ * KS_B * 4)              // 13312
#define SZ_W2  (O_ * H_ * 4)                // 1024
#define SZ_B1  (H_ * 4)                     // 256
#define SZ_B2  16
#define BUF_SZ 33152                         // 33040 padded to 128B
#define SMEM_TOTAL (2 * BUF_SZ)              // 66304

__device__ __forceinline__ uint32_t s2u(const void* p) {
    uint32_t a;
    asm("{ .reg .u64 t; cvta.to.shared.u64 t, %1; cvt.u32.u64 %0, t; }"
        : "=r"(a) : "l"(p));
    return a;
}

__device__ __forceinline__ void cpa16(uint32_t dst, const void* src) {
    asm volatile("cp.async.cg.shared.global [%0], [%1], 16;"
                 :: "r"(dst), "l"(src) : "memory");
}

__device__ __forceinline__ void ldsm4(uint32_t& r0, uint32_t& r1,
                                      uint32_t& r2, uint32_t& r3, uint32_t addr) {
    asm volatile("ldmatrix.sync.aligned.m8n8.x4.shared.b16 {%0,%1,%2,%3}, [%4];"
                 : "=r"(r0), "=r"(r1), "=r"(r2), "=r"(r3) : "r"(addr));
}

__device__ __forceinline__ void mma_tf32(float* d, const uint32_t* a, const uint32_t* b) {
    asm volatile(
        "mma.sync.aligned.m16n8k8.row.col.f32.tf32.tf32.f32 "
        "{%0,%1,%2,%3}, {%4,%5,%6,%7}, {%8,%9}, {%0,%1,%2,%3};"
        : "+f"(d[0]), "+f"(d[1]), "+f"(d[2]), "+f"(d[3])
        : "r"(a[0]), "r"(a[1]), "r"(a[2]), "r"(a[3]), "r"(b[0]), "r"(b[1]));
}

// stage one group's per-group data (items, W1_day, W1_var, W2, b1, b2) async
__device__ __forceinline__ void stage_group(
    uint32_t bufU, int g, int tid,
    const float* __restrict__ items, const float* __restrict__ W1_day,
    const float* __restrict__ W1_var, const float* __restrict__ W2,
    const float* __restrict__ b1, const float* __restrict__ b2)
{
    // items: 128 rows x 8 granules (k local 0..31)
    #pragma unroll
    for (int i = tid; i < 1024; i += THREADS) {
        int b = i >> 3, v4 = i & 7;
        cpa16(bufU + b * (KS_I * 4) + v4 * 16,
              items + ((size_t)b * G_ + g) * V_ + v4 * 4);
    }
    const uint32_t bB = bufU + SZ_AI;
    // W1_day -> Wcat cols 0..15
    #pragma unroll
    for (int i = tid; i < 256; i += THREADS) {
        int h = i >> 2, c4 = i & 3;
        cpa16(bB + h * (KS_B * 4) + c4 * 16,
              W1_day + (size_t)g * H_ * C_ + h * C_ + c4 * 4);
    }
    // W1_var -> Wcat cols 16..47
    #pragma unroll
    for (int i = tid; i < 512; i += THREADS) {
        int h = i >> 3, v4 = i & 7;
        cpa16(bB + h * (KS_B * 4) + 64 + v4 * 16,
              W1_var + (size_t)g * H_ * V_ + h * V_ + v4 * 4);
    }
    const uint32_t bW2 = bufU + SZ_AI + SZ_B;
    if (tid < 64) {
        cpa16(bW2 + tid * 16, W2 + (size_t)g * O_ * H_ + tid * 4);
    } else if (tid < 80) {
        cpa16(bW2 + SZ_W2 + (tid - 64) * 16, b1 + (size_t)g * H_ + (tid - 64) * 4);
    } else if (tid == 80) {
        cpa16(bW2 + SZ_W2 + SZ_B1, b2 + (size_t)g * O_);
    }
}

__global__ void __launch_bounds__(THREADS)
splitmlp_pipe_kernel(const float* __restrict__ day,
                     const float* __restrict__ items,
                     const float* __restrict__ W1_day,
                     const float* __restrict__ W1_var,
                     const float* __restrict__ b1,
                     const float* __restrict__ W2,
                     const float* __restrict__ b2,
                     float* __restrict__ out)
{
    extern __shared__ __align__(128) char sm[];
    const uint32_t sbase = s2u(sm);
    const int tid  = threadIdx.x;
    const int lane = tid & 31;
    const int wid  = tid >> 5;          // warp owns rows 32*wid..32*wid+31

    const int g0 = blockIdx.x;
    if (g0 >= G_) return;

    // ---- prologue: stage group0 into buf0 (commit #0) ----
    stage_group(sbase, g0, tid, items, W1_day, W1_var, W2, b1, b2);
    asm volatile("cp.async.commit_group;" ::: "memory");

    // ---- stage day transiently into buf1, pull fragments to registers ----
    #pragma unroll
    for (int i = tid; i < 512; i += THREADS) {       // 128 rows x 4 granules
        int b = i >> 2, c4 = i & 3;
        cpa16(sbase + BUF_SZ + b * (KS_D * 4) + c4 * 16, day + b * C_ + c4 * 4);
    }
    asm volatile("cp.async.commit_group;" ::: "memory");  // commit #1
    asm volatile("cp.async.wait_group 0;" ::: "memory");
    __syncthreads();

    const int rsel = lane & 15, hsel = (lane >> 4) * 16;
    uint32_t aday[2][2][4];                           // [ks][mt][4]
    {
        const uint32_t dayAddr =
            sbase + BUF_SZ + (32 * wid + rsel) * (KS_D * 4) + hsel;
        #pragma unroll
        for (int ks = 0; ks < 2; ks++)
            #pragma unroll
            for (int mt = 0; mt < 2; mt++)
                ldsm4(aday[ks][mt][0], aday[ks][mt][1],
                      aday[ks][mt][2], aday[ks][mt][3],
                      dayAddr + mt * 16 * (KS_D * 4) + ks * 32);
    }
    __syncthreads();    // everyone has day frags; buf1 may now be recycled

    int it = 0;
    for (int g = g0; g < G_; g += GRID, it++) {
        const uint32_t curU = sbase + (uint32_t)(it & 1) * BUF_SZ;
        const char*    curP = sm + (size_t)(it & 1) * BUF_SZ;

        const int gn = g + GRID;
        if (gn < G_) {
            stage_group(sbase + (uint32_t)((it + 1) & 1) * BUF_SZ,
                        gn, tid, items, W1_day, W1_var, W2, b1, b2);
            asm volatile("cp.async.commit_group;" ::: "memory");
            asm volatile("cp.async.wait_group 1;" ::: "memory");
        } else {
            asm volatile("cp.async.wait_group 0;" ::: "memory");
        }
        __syncthreads();

        // ---- fc1 mainloop: warp owns 32 rows, all 64 cols ----
        const uint32_t aiAddr = curU + (32 * wid + rsel) * (KS_I * 4) + hsel;
        const uint32_t bAddr  = curU + SZ_AI + rsel * (KS_B * 4) + hsel;

        float acc[2][8][4];
        #pragma unroll
        for (int mt = 0; mt < 2; mt++)
            #pragma unroll
            for (int nt = 0; nt < 8; nt++)
                #pragma unroll
                for (int c = 0; c < 4; c++)
                    acc[mt][nt][c] = 0.0f;

        #pragma unroll
        for (int ks = 0; ks < 6; ks++) {             // K = 48 = 6 x 8
            uint32_t areg[2][4];
            const uint32_t* a0;
            const uint32_t* a1;
            if (ks < 2) {                            // day (registers, no LDSM)
                a0 = aday[ks][0];
                a1 = aday[ks][1];
            } else {                                 // items (k 16..47)
                ldsm4(areg[0][0], areg[0][1], areg[0][2], areg[0][3],
                      aiAddr + (ks - 2) * 32);
                ldsm4(areg[1][0], areg[1][1], areg[1][2], areg[1][3],
                      aiAddr + 16 * (KS_I * 4) + (ks - 2) * 32);
                a0 = areg[0];
                a1 = areg[1];
            }
            uint32_t bf[8][2];
            #pragma unroll
            for (int np = 0; np < 4; np++) {
                uint32_t r0, r1, r2, r3;
                ldsm4(r0, r1, r2, r3, bAddr + np * 16 * (KS_B * 4) + ks * 32);
                bf[2 * np + 0][0] = r0; bf[2 * np + 0][1] = r2;
                bf[2 * np + 1][0] = r1; bf[2 * np + 1][1] = r3;
            }
            #pragma unroll
            for (int nt = 0; nt < 8; nt++) {
                mma_tf32(acc[0][nt], a0, bf[nt]);
                mma_tf32(acc[1][nt], a1, bf[nt]);
            }
        }

        // ---- epilogue: bias + ReLU + fc2 in registers ----
        const float* W2s = (const float*)(curP + SZ_AI + SZ_B);
        const float* b1s = (const float*)(curP + SZ_AI + SZ_B + SZ_W2);
        const float* b2s = (const float*)(curP + SZ_AI + SZ_B + SZ_W2 + SZ_B1);

        float y[4][4];
        #pragma unroll
        for (int j = 0; j < 4; j++)
            #pragma unroll
            for (int o = 0; o < O_; o++)
                y[j][o] = 0.0f;

        #pragma unroll
        for (int nt = 0; nt < 8; nt++) {
            const int h0 = nt * 8 + 2 * (lane & 3);
            float2 bb = *(const float2*)&b1s[h0];
            float2 w0 = *(const float2*)&W2s[0 * H_ + h0];
            float2 w1 = *(const float2*)&W2s[1 * H_ + h0];
            float2 w2 = *(const float2*)&W2s[2 * H_ + h0];
            float2 w3 = *(const float2*)&W2s[3 * H_ + h0];
            #pragma unroll
            for (int mt = 0; mt < 2; mt++)
                #pragma unroll
                for (int hh = 0; hh < 2; hh++) {
                    float v0 = fmaxf(acc[mt][nt][hh * 2 + 0] + bb.x, 0.0f);
                    float v1 = fmaxf(acc[mt][nt][hh * 2 + 1] + bb.y, 0.0f);
                    const int j = mt * 2 + hh;
                    y[j][0] = fmaf(v0, w0.x, fmaf(v1, w0.y, y[j][0]));
                    y[j][1] = fmaf(v0, w1.x, fmaf(v1, w1.y, y[j][1]));
                    y[j][2] = fmaf(v0, w2.x, fmaf(v1, w2.y, y[j][2]));
                    y[j][3] = fmaf(v0, w3.x, fmaf(v1, w3.y, y[j][3]));
                }
        }

        #pragma unroll
        for (int m = 1; m < 4; m <<= 1)
            #pragma unroll
            for (int j = 0; j < 4; j++)
                #pragma unroll
                for (int o = 0; o < O_; o++)
                    y[j][o] += __shfl_xor_sync(0xffffffffu, y[j][o], m);

        if ((lane & 3) == 0) {
            const int r = lane >> 2;
            #pragma unroll
            for (int mt = 0; mt < 2; mt++)
                #pragma unroll
                for (int hh = 0; hh < 2; hh++) {
                    const int j = mt * 2 + hh;
                    const int b = 32 * wid + 16 * mt + 8 * hh + r;
                    float4 o4;
                    o4.x = y[j][0] + b2s[0];
                    o4.y = y[j][1] + b2s[1];
                    o4.z = y[j][2] + b2s[2];
                    o4.w = y[j][3] + b2s[3];
                    *(float4*)(out + ((size_t)b * G_ + g) * O_) = o4;
                }
        }

        __syncthreads();   // buffer reuse: next-next stage writes over this one
    }
}

extern "C" void kernel_launch(void* const* d_in, const int* in_sizes, int n_in,
                              void* d_out, int out_size)
{
    const float* day    = (const float*)d_in[0];
    const float* items  = (const float*)d_in[1];
    const float* W1_day = (const float*)d_in[2];
    const float* W1_var = (const float*)d_in[3];
    const float* b1     = (const float*)d_in[4];
    const float* W2     = (const float*)d_in[5];
    const float* b2     = (const float*)d_in[6];
    float* out = (float*)d_out;

    static bool attr_done = false;
    if (!attr_done) {
        cudaFuncSetAttribute(splitmlp_pipe_kernel,
                             cudaFuncAttributeMaxDynamicSharedMemorySize, SMEM_TOTAL);
        attr_done = true;
    }
    splitmlp_pipe_kernel<<<GRID, THREADS, SMEM_TOTAL>>>(
        day, items, W1_day, W1_var, b1, W2, b2, out);
}

// round 13
// speedup vs baseline: 1.2531x; 1.0192x over previous
#include <cuda_runtime.h>
#include <cstdint>

// SplitMLP, tf32 mma.sync, persistent CTAs, double-buffered cp.async.
// R13 = R12 with KS_B fixed back to 52 (44 overflowed the 48-float Wcat row).
// Loop-invariant staging addresses, software-pipelined ldmatrix prefetch,
// streaming output stores.

#define B_ 128
#define C_ 16
#define V_ 32
#define H_ 64
#define O_ 4
#define G_ 10000

#define THREADS 128
#define GRID 444            // 3 CTAs/SM x 148 SMs, persistent

// smem row strides (floats) — ldmatrix-phase conflict-free
#define KS_D 20             // day staging (transient, buffer 1)
#define KS_I 36             // items tile: 128 x 32  (144B rows)
#define KS_B 52             // Wcat  tile:  64 x 48  (208B rows; >= 192B data!)

#define SZ_AI  (B_ * KS_I * 4)              // 18432
#define SZ_B   (H_ * KS_B * 4)              // 13312
#define SZ_W2  (O_ * H_ * 4)                // 1024
#define SZ_B1  (H_ * 4)                     // 256
#define SZ_B2  16
#define BUF_SZ 33152                         // 33040 padded to 128B
#define SMEM_TOTAL (2 * BUF_SZ)              // 66304

__device__ __forceinline__ uint32_t s2u(const void* p) {
    uint32_t a;
    asm("{ .reg .u64 t; cvta.to.shared.u64 t, %1; cvt.u32.u64 %0, t; }"
        : "=r"(a) : "l"(p));
    return a;
}

__device__ __forceinline__ void cpa16(uint32_t dst, const void* src) {
    asm volatile("cp.async.cg.shared.global [%0], [%1], 16;"
                 :: "r"(dst), "l"(src) : "memory");
}

__device__ __forceinline__ void ldsm4(uint32_t& r0, uint32_t& r1,
                                      uint32_t& r2, uint32_t& r3, uint32_t addr) {
    asm volatile("ldmatrix.sync.aligned.m8n8.x4.shared.b16 {%0,%1,%2,%3}, [%4];"
                 : "=r"(r0), "=r"(r1), "=r"(r2), "=r"(r3) : "r"(addr));
}

__device__ __forceinline__ void mma_tf32(float* d, const uint32_t* a, const uint32_t* b) {
    asm volatile(
        "mma.sync.aligned.m16n8k8.row.col.f32.tf32.tf32.f32 "
        "{%0,%1,%2,%3}, {%4,%5,%6,%7}, {%8,%9}, {%0,%1,%2,%3};"
        : "+f"(d[0]), "+f"(d[1]), "+f"(d[2]), "+f"(d[3])
        : "r"(a[0]), "r"(a[1]), "r"(a[2]), "r"(a[3]), "r"(b[0]), "r"(b[1]));
}

__device__ __forceinline__ void stcs4(float* p, float4 v) {
    asm volatile("st.global.cs.v4.f32 [%0], {%1,%2,%3,%4};"
                 :: "l"(p), "f"(v.x), "f"(v.y), "f"(v.z), "f"(v.w) : "memory");
}

__global__ void __launch_bounds__(THREADS)
splitmlp_pipe_kernel(const float* __restrict__ day,
                     const float* __restrict__ items,
                     const float* __restrict__ W1_day,
                     const float* __restrict__ W1_var,
                     const float* __restrict__ b1,
                     const float* __restrict__ W2,
                     const float* __restrict__ b2,
                     float* __restrict__ out)
{
    extern __shared__ __align__(128) char sm[];
    const uint32_t sbase = s2u(sm);
    const int tid  = threadIdx.x;
    const int lane = tid & 31;
    const int wid  = tid >> 5;          // warp owns rows 32*wid..32*wid+31

    const int g0 = blockIdx.x;
    if (g0 >= G_) return;

    // ---- loop-invariant staging state (pointers advance by constants) ----
    const float* pIt = items + ((size_t)(tid >> 3) * G_ + g0) * V_ + (tid & 7) * 4;
    const float* pWd = W1_day + (size_t)g0 * H_ * C_ + (tid >> 2) * C_ + (tid & 3) * 4;
    const float* pWv = W1_var + (size_t)g0 * H_ * V_ + (tid >> 3) * V_ + (tid & 7) * 4;
    const float* pX  = nullptr;
    uint32_t dX = 0;  size_t advX = 0;
    if (tid < 64)       { pX = W2 + (size_t)g0 * O_ * H_ + tid * 4;
                          dX = SZ_AI + SZ_B + tid * 16;         advX = (size_t)GRID * O_ * H_; }
    else if (tid < 80)  { pX = b1 + (size_t)g0 * H_ + (tid - 64) * 4;
                          dX = SZ_AI + SZ_B + SZ_W2 + (tid - 64) * 16; advX = (size_t)GRID * H_; }
    else if (tid == 80) { pX = b2 + (size_t)g0 * O_;
                          dX = SZ_AI + SZ_B + SZ_W2 + SZ_B1;    advX = (size_t)GRID * O_; }

    const uint32_t dAI = (tid >> 3) * (KS_I * 4) + (tid & 7) * 16;
    const uint32_t dBd = SZ_AI + (tid >> 2) * (KS_B * 4) + (tid & 3) * 16;
    const uint32_t dBv = SZ_AI + (tid >> 3) * (KS_B * 4) + 64 + (tid & 7) * 16;

    // stage current group's data into bufU, then advance pointers
    #define STAGE(bufU)                                                          \
        do {                                                                     \
            _Pragma("unroll")                                                    \
            for (int j = 0; j < 8; j++)                                          \
                cpa16((bufU) + dAI + j * (16 * KS_I * 4),                        \
                      pIt + (size_t)j * 16 * G_ * V_);                           \
            _Pragma("unroll")                                                    \
            for (int j = 0; j < 2; j++)                                          \
                cpa16((bufU) + dBd + j * (32 * KS_B * 4), pWd + j * 32 * C_);    \
            _Pragma("unroll")                                                    \
            for (int j = 0; j < 4; j++)                                          \
                cpa16((bufU) + dBv + j * (16 * KS_B * 4), pWv + j * 16 * V_);    \
            if (pX) cpa16((bufU) + dX, pX);                                      \
            pIt += (size_t)GRID * V_;                                            \
            pWd += (size_t)GRID * H_ * C_;                                       \
            pWv += (size_t)GRID * H_ * V_;                                       \
            pX  += advX;                                                         \
        } while (0)

    // ---- prologue: stage group0 into buf0 (commit #0) ----
    STAGE(sbase);
    asm volatile("cp.async.commit_group;" ::: "memory");

    // ---- stage day transiently into buf1, pull fragments to registers ----
    #pragma unroll
    for (int i = tid; i < 512; i += THREADS) {
        int b = i >> 2, c4 = i & 3;
        cpa16(sbase + BUF_SZ + b * (KS_D * 4) + c4 * 16, day + b * C_ + c4 * 4);
    }
    asm volatile("cp.async.commit_group;" ::: "memory");
    asm volatile("cp.async.wait_group 0;" ::: "memory");
    __syncthreads();

    const int rsel = lane & 15, hsel = (lane >> 4) * 16;
    uint32_t aday[2][2][4];                           // [ks][mt][4]
    {
        const uint32_t dayAddr =
            sbase + BUF_SZ + (32 * wid + rsel) * (KS_D * 4) + hsel;
        #pragma unroll
        for (int ks = 0; ks < 2; ks++)
            #pragma unroll
            for (int mt = 0; mt < 2; mt++)
                ldsm4(aday[ks][mt][0], aday[ks][mt][1],
                      aday[ks][mt][2], aday[ks][mt][3],
                      dayAddr + mt * 16 * (KS_D * 4) + ks * 32);
    }
    __syncthreads();    // day frags in regs; buf1 recyclable

    int it = 0;
    for (int g = g0; g < G_; g += GRID, it++) {
        const uint32_t curU = sbase + (uint32_t)(it & 1) * BUF_SZ;
        const char*    curP = sm + (size_t)(it & 1) * BUF_SZ;

        if (g + GRID < G_) {
            STAGE(sbase + (uint32_t)((it + 1) & 1) * BUF_SZ);
            asm volatile("cp.async.commit_group;" ::: "memory");
            asm volatile("cp.async.wait_group 1;" ::: "memory");
        } else {
            asm volatile("cp.async.wait_group 0;" ::: "memory");
        }
        __syncthreads();

        // ---- fc1 mainloop, software-pipelined over ks ----
        const uint32_t aiAddr = curU + (32 * wid + rsel) * (KS_I * 4) + hsel;
        const uint32_t bAddr  = curU + SZ_AI + rsel * (KS_B * 4) + hsel;

        float acc[2][8][4];
        #pragma unroll
        for (int mt = 0; mt < 2; mt++)
            #pragma unroll
            for (int nt = 0; nt < 8; nt++)
                #pragma unroll
                for (int c = 0; c < 4; c++)
                    acc[mt][nt][c] = 0.0f;

        uint32_t bf[2][8][2];      // double-buffered B fragments
        uint32_t areg[2][2][4];    // double-buffered items-A fragments

        // preload ks=0 B frags
        {
            uint32_t r0, r1, r2, r3;
            #pragma unroll
            for (int np = 0; np < 4; np++) {
                ldsm4(r0, r1, r2, r3, bAddr + np * (16 * KS_B * 4));
                bf[0][2 * np + 0][0] = r0; bf[0][2 * np + 0][1] = r2;
                bf[0][2 * np + 1][0] = r1; bf[0][2 * np + 1][1] = r3;
            }
        }

        #pragma unroll
        for (int ks = 0; ks < 6; ks++) {
            const int cb = ks & 1, nb = cb ^ 1;
            // prefetch ks+1 fragments before issuing this step's MMAs
            if (ks < 5) {
                uint32_t r0, r1, r2, r3;
                #pragma unroll
                for (int np = 0; np < 4; np++) {
                    ldsm4(r0, r1, r2, r3,
                          bAddr + np * (16 * KS_B * 4) + (ks + 1) * 32);
                    bf[nb][2 * np + 0][0] = r0; bf[nb][2 * np + 0][1] = r2;
                    bf[nb][2 * np + 1][0] = r1; bf[nb][2 * np + 1][1] = r3;
                }
                if (ks + 1 >= 2) {
                    ldsm4(areg[nb][0][0], areg[nb][0][1],
                          areg[nb][0][2], areg[nb][0][3],
                          aiAddr + (ks - 1) * 32);
                    ldsm4(areg[nb][1][0], areg[nb][1][1],
                          areg[nb][1][2], areg[nb][1][3],
                          aiAddr + 16 * (KS_I * 4) + (ks - 1) * 32);
                }
            }
            const uint32_t* a0 = (ks < 2) ? aday[ks][0] : areg[cb][0];
            const uint32_t* a1 = (ks < 2) ? aday[ks][1] : areg[cb][1];
            #pragma unroll
            for (int nt = 0; nt < 8; nt++) {
                mma_tf32(acc[0][nt], a0, bf[cb][nt]);
                mma_tf32(acc[1][nt], a1, bf[cb][nt]);
            }
        }

        // ---- epilogue: bias + ReLU + fc2 in registers ----
        const float* W2s = (const float*)(curP + SZ_AI + SZ_B);
        const float* b1s = (const float*)(curP + SZ_AI + SZ_B + SZ_W2);
        const float* b2s = (const float*)(curP + SZ_AI + SZ_B + SZ_W2 + SZ_B1);

        float y[4][4];
        #pragma unroll
        for (int j = 0; j < 4; j++)
            #pragma unroll
            for (int o = 0; o < O_; o++)
                y[j][o] = 0.0f;

        #pragma unroll
        for (int nt = 0; nt < 8; nt++) {
            const int h0 = nt * 8 + 2 * (lane & 3);
            float2 bb = *(const float2*)&b1s[h0];
            float2 w0 = *(const float2*)&W2s[0 * H_ + h0];
            float2 w1 = *(const float2*)&W2s[1 * H_ + h0];
            float2 w2 = *(const float2*)&W2s[2 * H_ + h0];
            float2 w3 = *(const float2*)&W2s[3 * H_ + h0];
            #pragma unroll
            for (int mt = 0; mt < 2; mt++)
                #pragma unroll
                for (int hh = 0; hh < 2; hh++) {
                    float v0 = fmaxf(acc[mt][nt][hh * 2 + 0] + bb.x, 0.0f);
                    float v1 = fmaxf(acc[mt][nt][hh * 2 + 1] + bb.y, 0.0f);
                    const int j = mt * 2 + hh;
                    y[j][0] = fmaf(v0, w0.x, fmaf(v1, w0.y, y[j][0]));
                    y[j][1] = fmaf(v0, w1.x, fmaf(v1, w1.y, y[j][1]));
                    y[j][2] = fmaf(v0, w2.x, fmaf(v1, w2.y, y[j][2]));
                    y[j][3] = fmaf(v0, w3.x, fmaf(v1, w3.y, y[j][3]));
                }
        }

        #pragma unroll
        for (int m = 1; m < 4; m <<= 1)
            #pragma unroll
            for (int j = 0; j < 4; j++)
                #pragma unroll
                for (int o = 0; o < O_; o++)
                    y[j][o] += __shfl_xor_sync(0xffffffffu, y[j][o], m);

        if ((lane & 3) == 0) {
            const int r = lane >> 2;
            #pragma unroll
            for (int mt = 0; mt < 2; mt++)
                #pragma unroll
                for (int hh = 0; hh < 2; hh++) {
                    const int j = mt * 2 + hh;
                    const int b = 32 * wid + 16 * mt + 8 * hh + r;
                    float4 o4;
                    o4.x = y[j][0] + b2s[0];
                    o4.y = y[j][1] + b2s[1];
                    o4.z = y[j][2] + b2s[2];
                    o4.w = y[j][3] + b2s[3];
                    stcs4(out + ((size_t)b * G_ + g) * O_, o4);
                }
        }

        __syncthreads();   // protect cur buffer before next-next stage overwrite
    }
    #undef STAGE
}

extern "C" void kernel_launch(void* const* d_in, const int* in_sizes, int n_in,
                              void* d_out, int out_size)
{
    const float* day    = (const float*)d_in[0];
    const float* items  = (const float*)d_in[1];
    const float* W1_day = (const float*)d_in[2];
    const float* W1_var = (const float*)d_in[3];
    const float* b1     = (const float*)d_in[4];
    const float* W2     = (const float*)d_in[5];
    const float* b2     = (const float*)d_in[6];
    float* out = (float*)d_out;

    static bool attr_done = false;
    if (!attr_done) {
        cudaFuncSetAttribute(splitmlp_pipe_kernel,
                             cudaFuncAttributeMaxDynamicSharedMemorySize, SMEM_TOTAL);
        attr_done = true;
    }
    splitmlp_pipe_kernel<<<GRID, THREADS, SMEM_TOTAL>>>(
        day, items, W1_day, W1_var, b1, W2, b2, out);
}